// round 12
// baseline (speedup 1.0000x reference)
#include <cuda_runtime.h>
#include <cstdint>

#define HID     100
#define NREG    (HID + 1)
#define MCAND   50
#define NTOP    32
#define NITER   100
#define NBATCH  4096
#define TPB     128

// ---------------------------------------------------------------------------
// Threefry-2x32 (20 rounds), identical to jax._src.prng
// ---------------------------------------------------------------------------
__device__ __forceinline__ void tf2x32(uint32_t k0, uint32_t k1,
                                       uint32_t x0, uint32_t x1,
                                       uint32_t &o0, uint32_t &o1) {
  uint32_t ks2 = k0 ^ k1 ^ 0x1BD11BDAu;
#define TFROT(r) { x0 += x1; x1 = __funnelshift_l(x1, x1, (r)); x1 ^= x0; }
  x0 += k0; x1 += k1;
  TFROT(13) TFROT(15) TFROT(26) TFROT(6)
  x0 += k1;  x1 += ks2 + 1u;
  TFROT(17) TFROT(29) TFROT(16) TFROT(24)
  x0 += ks2; x1 += k0 + 2u;
  TFROT(13) TFROT(15) TFROT(26) TFROT(6)
  x0 += k0;  x1 += k1 + 3u;
  TFROT(17) TFROT(29) TFROT(16) TFROT(24)
  x0 += k1;  x1 += ks2 + 4u;
  TFROT(13) TFROT(15) TFROT(26) TFROT(6)
  x0 += ks2; x1 += k0 + 5u;
#undef TFROT
  o0 = x0; o1 = x1;
}

__device__ __forceinline__ uint32_t jax_bits(uint32_t ka, uint32_t kb, uint32_t idx) {
  uint32_t o0, o1;
  tf2x32(ka, kb, 0u, idx, o0, o1);
  return o0 ^ o1;
}

__device__ __forceinline__ float u01_from_bits(uint32_t bits) {
  return __uint_as_float((bits >> 9) | 0x3F800000u) - 1.0f;
}

// XLA ErfInv32 (Giles) polynomial — matches lax.erf_inv lowering
__device__ __forceinline__ float erfinv_f32(float x) {
  float w = -log1pf(-x * x);
  float p;
  if (w < 5.0f) {
    w -= 2.5f;
    p = 2.81022636e-08f;
    p = fmaf(p, w, 3.43273939e-07f);
    p = fmaf(p, w, -3.5233877e-06f);
    p = fmaf(p, w, -4.39150654e-06f);
    p = fmaf(p, w, 0.00021858087f);
    p = fmaf(p, w, -0.00125372503f);
    p = fmaf(p, w, -0.00417768164f);
    p = fmaf(p, w, 0.246640727f);
    p = fmaf(p, w, 1.50140941f);
  } else {
    w = sqrtf(w) - 3.0f;
    p = -0.000200214257f;
    p = fmaf(p, w, 0.000100950558f);
    p = fmaf(p, w, 0.00134934322f);
    p = fmaf(p, w, -0.00367342844f);
    p = fmaf(p, w, 0.00573950773f);
    p = fmaf(p, w, -0.0076224613f);
    p = fmaf(p, w, 0.00943887047f);
    p = fmaf(p, w, 1.00167406f);
    p = fmaf(p, w, 2.83297682f);
  }
  return p * x;
}

// ---------------------------------------------------------------------------
// Piecewise-linear CEM kernel. One CTA per batch row.
// h_k(angle) = relu(a_k + b_k*angle) is PWL in angle with knee t_k = -a_k/b_k
// (a_k, b_k fixed per row). Precompute e_j(angle) = A[r][j] + B[r][j]*angle
// per sorted-knee region r. Each candidate eval is then O(HID), not O(HID^2).
// ---------------------------------------------------------------------------
__global__ void __launch_bounds__(TPB, 2) cem_kernel(
    const float* __restrict__ states, const float* __restrict__ W1,
    const float* __restrict__ b1,     const float* __restrict__ W2,
    const float* __restrict__ b2,     const float* __restrict__ W3,
    const float* __restrict__ b3,     float* __restrict__ out) {

  extern __shared__ __align__(16) char smraw[];
  float2*   AB    = reinterpret_cast<float2*>(smraw);          // [NREG][HID]
  float*    tsort = reinterpret_cast<float*>(AB + NREG * HID); // [HID+1] (+inf sentinel)
  float*    tun   = tsort + (HID + 1);                          // [HID]
  float*    a_arr = tun + HID;                                  // [HID]
  float*    b_arr = a_arr + HID;                                // [HID]
  float*    w3s   = b_arr + HID;                                // [HID]
  int*      ord   = reinterpret_cast<int*>(w3s + HID);          // [HID]
  float*    qs    = reinterpret_cast<float*>(ord + HID);        // [MCAND]
  float*    angs  = qs + MCAND;                                 // [MCAND]
  uint32_t* keyA  = reinterpret_cast<uint32_t*>(angs + MCAND);  // [NITER-1]
  uint32_t* keyB  = keyA + (NITER - 1);                         // [NITER-1]
  float*    musd  = reinterpret_cast<float*>(keyB + (NITER - 1)); // [2]

  const int tid = threadIdx.x;
  const int row = blockIdx.x;
  const float b3v = b3[0];

  // ================= per-row precompute =================
  if (tid < HID) {
    float s0 = states[2 * row], s1 = states[2 * row + 1];
    float a = fmaf(s1, W1[HID + tid], fmaf(s0, W1[tid], b1[tid]));
    float b = W1[2 * HID + tid];
    a_arr[tid] = a;
    b_arr[tid] = b;
    tun[tid]   = -a / b;
    w3s[tid]   = W3[tid];
  }
  if (tid == HID) tsort[HID] = __int_as_float(0x7F800000);  // +inf sentinel
  // PRNG setup: key = jax.random.key(42) => (0,42); partitionable split
  uint32_t k0a, k0b, klA, klB;
  tf2x32(0u, 42u, 0u, 0u, k0a, k0b);
  tf2x32(0u, 42u, 0u, 1u, klA, klB);
  if (tid < NITER - 1) {
    uint32_t ya, yb;
    tf2x32(klA, klB, 0u, (uint32_t)tid, ya, yb);
    keyA[tid] = ya; keyB[tid] = yb;
  }
  __syncthreads();

  // rank-sort knees (stable)
  if (tid < HID) {
    float tme = tun[tid];
    int rank = 0;
#pragma unroll 4
    for (int m = 0; m < HID; ++m) {
      float tm = tun[m];
      rank += (tm < tme) || (tm == tme && m < tid);
    }
    ord[rank]   = tid;
    tsort[rank] = tme;
  }
  __syncthreads();

  // region-0 coefficients (angle -> -inf: active iff b_k < 0), b2 folded in;
  // then per-knee deltas into regions 1..100
  if (tid < HID) {
    float A = b2[tid], B = 0.0f;
#pragma unroll 4
    for (int k = 0; k < HID; ++k) {
      float bk = b_arr[k];
      if (bk < 0.0f) {
        float w = W2[k * HID + tid];
        A = fmaf(w, a_arr[k], A);
        B = fmaf(w, bk, B);
      }
    }
    AB[tid] = make_float2(A, B);
#pragma unroll 4
    for (int r = 0; r < HID; ++r) {
      int k = ord[r];
      float ak = a_arr[k], bk = b_arr[k];
      float w = W2[k * HID + tid];
      w = (bk > 0.0f) ? w : -w;    // crossing t_k upward: b>0 activates, b<0 deactivates
      AB[(r + 1) * HID + tid] = make_float2(w * ak, w * bk);
    }
  }
  __syncthreads();

  // prefix-sum deltas over regions (per-j serial, j-parallel)
  if (tid < HID) {
    float2 acc = AB[tid];
#pragma unroll 4
    for (int r = 1; r < NREG; ++r) {
      float2 d = AB[r * HID + tid];
      acc.x += d.x; acc.y += d.y;
      AB[r * HID + tid] = acc;
    }
  }

  // iteration-0 angles: uniform [0,1)
  if (tid < MCAND)
    angs[tid] = u01_from_bits(jax_bits(k0a, k0b, (uint32_t)(row * MCAND + tid)));
  __syncthreads();

  // ================= CEM loop =================
  const float LO    = __uint_as_float(0xBF7FFFFFu);  // nextafter(-1,0)
  const float SQRT2 = __uint_as_float(0x3FB504F3u);
  const float TWOPI = __uint_as_float(0x40C90FDBu);
  const int lane = tid & 31, wid = tid >> 5;
  const int c   = tid >> 1, half = tid & 1;           // 2 threads per candidate
  const bool cval = (c < MCAND);
  const int cs  = cval ? c : 0;                       // clamped for idle threads

  for (int it = 0; it < NITER - 1; ++it) {
    // ---- candidate eval: ALL threads run this (converged shuffles) ----
    {
      float angle = angs[cs];
      int lo = 0, hi = HID;
#pragma unroll 7
      for (int s = 0; s < 7; ++s) {     // count knees < angle; tsort[100]=+inf
        int mid = (lo + hi) >> 1;
        if (tsort[mid] < angle) lo = mid + 1; else hi = mid;
      }
      const float4* rp = reinterpret_cast<const float4*>(AB + lo * HID + half * (HID / 2));
      const float*  wp = w3s + half * (HID / 2);
      float q0 = 0.f, q1 = 0.f;
#pragma unroll
      for (int jj = 0; jj < HID / 4; ++jj) {
        float4 v = rp[jj];
        float e0 = fmaf(v.y, angle, v.x);
        float e1 = fmaf(v.w, angle, v.z);
        q0 = fmaf(fmaxf(e0, 0.f), wp[2 * jj],     q0);
        q1 = fmaf(fmaxf(e1, 0.f), wp[2 * jj + 1], q1);
      }
      float qp = q0 + q1;
      qp += __shfl_xor_sync(0xffffffffu, qp, 1);      // full warp converged
      if (cval && half == 0) qs[c] = qp + b3v;
    }
    __syncthreads();

    // ---- top-32 stats on warp 0 ----
    if (wid == 0) {
      const bool has2 = lane < (MCAND - 32);
      const float q1v = qs[lane];
      const float q2v = qs[has2 ? 32 + lane : 0];
      int rank1 = 0, rank2 = 0;
#pragma unroll
      for (int cc = 0; cc < MCAND; ++cc) {
        float qv = qs[cc];
        rank1 += (qv > q1v) || (qv == q1v && cc < lane);
        rank2 += (qv > q2v) || (qv == q2v && cc < 32 + lane);
      }
      const bool s1 = rank1 < NTOP;
      const bool s2 = has2 && (rank2 < NTOP);
      float s = (s1 ? q1v : 0.f) + (s2 ? q2v : 0.f);
#pragma unroll
      for (int o = 16; o > 0; o >>= 1) s += __shfl_xor_sync(0xffffffffu, s, o);
      const float mu = s * (1.0f / NTOP);
      float d = (s1 ? (q1v - mu) * (q1v - mu) : 0.f) + (s2 ? (q2v - mu) * (q2v - mu) : 0.f);
#pragma unroll
      for (int o = 16; o > 0; o >>= 1) d += __shfl_xor_sync(0xffffffffu, d, o);
      if (lane == 0) {
        musd[0] = mu;
        musd[1] = sqrtf(d * (1.0f / (NTOP - 1)));
      }
    }
    __syncthreads();

    if (it == NITER - 2) {
      if (tid == 0) out[row] = musd[0] * TWOPI;
      break;
    }

    // ---- sample next angles: N(mu_q, std_q) ----
    if (tid < MCAND) {
      uint32_t bits = jax_bits(keyA[it], keyB[it], (uint32_t)(row * MCAND + tid));
      float u = fmaxf(LO, fmaf(u01_from_bits(bits), 2.0f, LO));
      angs[tid] = fmaf(musd[1], SQRT2 * erfinv_f32(u), musd[0]);
    }
    __syncthreads();
  }
}

extern "C" void kernel_launch(void* const* d_in, const int* in_sizes, int n_in,
                              void* d_out, int out_size) {
  const float* states = (const float*)d_in[0];
  const float* W1     = (const float*)d_in[1];
  const float* b1     = (const float*)d_in[2];
  const float* W2     = (const float*)d_in[3];
  const float* b2     = (const float*)d_in[4];
  const float* W3     = (const float*)d_in[5];
  const float* b3     = (const float*)d_in[6];
  float* out          = (float*)d_out;
  (void)in_sizes; (void)n_in; (void)out_size;

  const size_t SMEM_BYTES =
      sizeof(float2) * NREG * HID +        // AB table
      sizeof(float) * (HID + 1) +          // tsort (+sentinel)
      sizeof(float) * HID * 4 +            // tun, a, b, w3
      sizeof(int) * HID +                  // ord
      sizeof(float) * MCAND * 2 +          // qs, angs
      sizeof(uint32_t) * (NITER - 1) * 2 + // keys
      sizeof(float) * 2 + 64;              // musd + pad

  cudaFuncSetAttribute(cem_kernel, cudaFuncAttributeMaxDynamicSharedMemorySize,
                       (int)SMEM_BYTES);
  cem_kernel<<<NBATCH, TPB, SMEM_BYTES>>>(states, W1, b1, W2, b2, W3, b3, out);
}

// round 13
// speedup vs baseline: 1.6425x; 1.6425x over previous
#include <cuda_runtime.h>
#include <cstdint>

#define HID     100
#define NREG    (HID + 1)
#define MCAND   50
#define NTOP    32
#define NITER   100
#define NBATCH  4096
#define TPB     128

// ---------------------------------------------------------------------------
// Threefry-2x32 (20 rounds), identical to jax._src.prng
// ---------------------------------------------------------------------------
__device__ __forceinline__ void tf2x32(uint32_t k0, uint32_t k1,
                                       uint32_t x0, uint32_t x1,
                                       uint32_t &o0, uint32_t &o1) {
  uint32_t ks2 = k0 ^ k1 ^ 0x1BD11BDAu;
#define TFROT(r) { x0 += x1; x1 = __funnelshift_l(x1, x1, (r)); x1 ^= x0; }
  x0 += k0; x1 += k1;
  TFROT(13) TFROT(15) TFROT(26) TFROT(6)
  x0 += k1;  x1 += ks2 + 1u;
  TFROT(17) TFROT(29) TFROT(16) TFROT(24)
  x0 += ks2; x1 += k0 + 2u;
  TFROT(13) TFROT(15) TFROT(26) TFROT(6)
  x0 += k0;  x1 += k1 + 3u;
  TFROT(17) TFROT(29) TFROT(16) TFROT(24)
  x0 += k1;  x1 += ks2 + 4u;
  TFROT(13) TFROT(15) TFROT(26) TFROT(6)
  x0 += ks2; x1 += k0 + 5u;
#undef TFROT
  o0 = x0; o1 = x1;
}

__device__ __forceinline__ uint32_t jax_bits(uint32_t ka, uint32_t kb, uint32_t idx) {
  uint32_t o0, o1;
  tf2x32(ka, kb, 0u, idx, o0, o1);
  return o0 ^ o1;
}

__device__ __forceinline__ float u01_from_bits(uint32_t bits) {
  return __uint_as_float((bits >> 9) | 0x3F800000u) - 1.0f;
}

// XLA ErfInv32 (Giles) polynomial — matches lax.erf_inv lowering
__device__ __forceinline__ float erfinv_f32(float x) {
  float w = -log1pf(-x * x);
  float p;
  if (w < 5.0f) {
    w -= 2.5f;
    p = 2.81022636e-08f;
    p = fmaf(p, w, 3.43273939e-07f);
    p = fmaf(p, w, -3.5233877e-06f);
    p = fmaf(p, w, -4.39150654e-06f);
    p = fmaf(p, w, 0.00021858087f);
    p = fmaf(p, w, -0.00125372503f);
    p = fmaf(p, w, -0.00417768164f);
    p = fmaf(p, w, 0.246640727f);
    p = fmaf(p, w, 1.50140941f);
  } else {
    w = sqrtf(w) - 3.0f;
    p = -0.000200214257f;
    p = fmaf(p, w, 0.000100950558f);
    p = fmaf(p, w, 0.00134934322f);
    p = fmaf(p, w, -0.00367342844f);
    p = fmaf(p, w, 0.00573950773f);
    p = fmaf(p, w, -0.0076224613f);
    p = fmaf(p, w, 0.00943887047f);
    p = fmaf(p, w, 1.00167406f);
    p = fmaf(p, w, 2.83297682f);
  }
  return p * x;
}

// ---------------------------------------------------------------------------
// Piecewise-linear CEM kernel. One CTA per batch row.
// h_k(angle) = relu(a_k + b_k*angle) is PWL in angle with knee t_k = -a_k/b_k
// (a_k, b_k fixed per row). Precompute e_j(angle) = A[r][j] + B[r][j]*angle
// per sorted-knee region r. Each candidate eval is then O(HID), not O(HID^2).
// ---------------------------------------------------------------------------
__global__ void __launch_bounds__(TPB, 2) cem_kernel(
    const float* __restrict__ states, const float* __restrict__ W1,
    const float* __restrict__ b1,     const float* __restrict__ W2,
    const float* __restrict__ b2,     const float* __restrict__ W3,
    const float* __restrict__ b3,     float* __restrict__ out) {

  extern __shared__ __align__(16) char smraw[];
  float2*   AB    = reinterpret_cast<float2*>(smraw);          // [NREG][HID]
  float*    tsort = reinterpret_cast<float*>(AB + NREG * HID); // [HID+1] (+inf sentinel)
  float*    tun   = tsort + (HID + 1);                          // [HID]
  float*    a_arr = tun + HID;                                  // [HID]
  float*    b_arr = a_arr + HID;                                // [HID]
  float*    w3s   = b_arr + HID;                                // [HID]
  int*      ord   = reinterpret_cast<int*>(w3s + HID);          // [HID]
  float*    qs    = reinterpret_cast<float*>(ord + HID);        // [MCAND]
  float*    angs  = qs + MCAND;                                 // [MCAND]
  uint32_t* keyA  = reinterpret_cast<uint32_t*>(angs + MCAND);  // [NITER-1]
  uint32_t* keyB  = keyA + (NITER - 1);                         // [NITER-1]
  float*    musd  = reinterpret_cast<float*>(keyB + (NITER - 1)); // [2]

  const int tid = threadIdx.x;
  const int row = blockIdx.x;
  const float b3v = b3[0];

  // ================= per-row precompute =================
  if (tid < HID) {
    float s0 = states[2 * row], s1 = states[2 * row + 1];
    float a = fmaf(s1, W1[HID + tid], fmaf(s0, W1[tid], b1[tid]));
    float b = W1[2 * HID + tid];
    a_arr[tid] = a;
    b_arr[tid] = b;
    tun[tid]   = -a / b;
    w3s[tid]   = W3[tid];
  }
  if (tid == HID) tsort[HID] = __int_as_float(0x7F800000);  // +inf sentinel
  // PRNG setup: key = jax.random.key(42) => (0,42); partitionable split
  uint32_t k0a, k0b, klA, klB;
  tf2x32(0u, 42u, 0u, 0u, k0a, k0b);
  tf2x32(0u, 42u, 0u, 1u, klA, klB);
  if (tid < NITER - 1) {
    uint32_t ya, yb;
    tf2x32(klA, klB, 0u, (uint32_t)tid, ya, yb);
    keyA[tid] = ya; keyB[tid] = yb;
  }
  __syncthreads();

  // rank-sort knees (stable)
  if (tid < HID) {
    float tme = tun[tid];
    int rank = 0;
#pragma unroll 4
    for (int m = 0; m < HID; ++m) {
      float tm = tun[m];
      rank += (tm < tme) || (tm == tme && m < tid);
    }
    ord[rank]   = tid;
    tsort[rank] = tme;
  }
  __syncthreads();

  // region-0 coefficients (angle -> -inf: active iff b_k < 0), b2 folded in;
  // then per-knee deltas into regions 1..100
  if (tid < HID) {
    float A = b2[tid], B = 0.0f;
#pragma unroll 4
    for (int k = 0; k < HID; ++k) {
      float bk = b_arr[k];
      if (bk < 0.0f) {
        float w = W2[k * HID + tid];
        A = fmaf(w, a_arr[k], A);
        B = fmaf(w, bk, B);
      }
    }
    AB[tid] = make_float2(A, B);
#pragma unroll 4
    for (int r = 0; r < HID; ++r) {
      int k = ord[r];
      float ak = a_arr[k], bk = b_arr[k];
      float w = W2[k * HID + tid];
      w = (bk > 0.0f) ? w : -w;    // crossing t_k upward: b>0 activates, b<0 deactivates
      AB[(r + 1) * HID + tid] = make_float2(w * ak, w * bk);
    }
  }
  __syncthreads();

  // prefix-sum deltas over regions (per-j serial, j-parallel)
  if (tid < HID) {
    float2 acc = AB[tid];
#pragma unroll 4
    for (int r = 1; r < NREG; ++r) {
      float2 d = AB[r * HID + tid];
      acc.x += d.x; acc.y += d.y;
      AB[r * HID + tid] = acc;
    }
  }

  // iteration-0 angles: uniform [0,1)
  if (tid < MCAND)
    angs[tid] = u01_from_bits(jax_bits(k0a, k0b, (uint32_t)(row * MCAND + tid)));
  __syncthreads();

  // ================= CEM loop =================
  const float LO    = __uint_as_float(0xBF7FFFFFu);  // nextafter(-1,0)
  const float SQRT2 = __uint_as_float(0x3FB504F3u);
  const float TWOPI = __uint_as_float(0x40C90FDBu);
  const int lane = tid & 31, wid = tid >> 5;
  const int c   = tid >> 1, half = tid & 1;           // 2 threads per candidate
  const bool cval = (c < MCAND);
  const int cs  = cval ? c : 0;                       // clamped for idle threads

  for (int it = 0; it < NITER - 1; ++it) {
    // ---- candidate eval: ALL threads run this (converged shuffles) ----
    {
      float angle = angs[cs];
      int lo = 0, hi = HID;
#pragma unroll 7
      for (int s = 0; s < 7; ++s) {     // count knees < angle; tsort[100]=+inf
        int mid = (lo + hi) >> 1;
        if (tsort[mid] < angle) lo = mid + 1; else hi = mid;
      }
      const float4* rp = reinterpret_cast<const float4*>(AB + lo * HID + half * (HID / 2));
      const float*  wp = w3s + half * (HID / 2);
      float q0 = 0.f, q1 = 0.f;
#pragma unroll
      for (int jj = 0; jj < HID / 4; ++jj) {
        float4 v = rp[jj];
        float e0 = fmaf(v.y, angle, v.x);
        float e1 = fmaf(v.w, angle, v.z);
        q0 = fmaf(fmaxf(e0, 0.f), wp[2 * jj],     q0);
        q1 = fmaf(fmaxf(e1, 0.f), wp[2 * jj + 1], q1);
      }
      float qp = q0 + q1;
      qp += __shfl_xor_sync(0xffffffffu, qp, 1);      // full warp converged
      if (cval && half == 0) qs[c] = qp + b3v;
    }
    __syncthreads();

    // ---- top-32 stats on warp 0 ----
    if (wid == 0) {
      const bool has2 = lane < (MCAND - 32);
      const float q1v = qs[lane];
      const float q2v = qs[has2 ? 32 + lane : 0];
      int rank1 = 0, rank2 = 0;
#pragma unroll
      for (int cc = 0; cc < MCAND; ++cc) {
        float qv = qs[cc];
        rank1 += (qv > q1v) || (qv == q1v && cc < lane);
        rank2 += (qv > q2v) || (qv == q2v && cc < 32 + lane);
      }
      const bool s1 = rank1 < NTOP;
      const bool s2 = has2 && (rank2 < NTOP);
      float s = (s1 ? q1v : 0.f) + (s2 ? q2v : 0.f);
#pragma unroll
      for (int o = 16; o > 0; o >>= 1) s += __shfl_xor_sync(0xffffffffu, s, o);
      const float mu = s * (1.0f / NTOP);
      float d = (s1 ? (q1v - mu) * (q1v - mu) : 0.f) + (s2 ? (q2v - mu) * (q2v - mu) : 0.f);
#pragma unroll
      for (int o = 16; o > 0; o >>= 1) d += __shfl_xor_sync(0xffffffffu, d, o);
      if (lane == 0) {
        musd[0] = mu;
        musd[1] = sqrtf(d * (1.0f / (NTOP - 1)));
      }
    }
    __syncthreads();

    if (it == NITER - 2) {
      if (tid == 0) out[row] = musd[0] * TWOPI;
      break;
    }

    // ---- sample next angles: N(mu_q, std_q) ----
    if (tid < MCAND) {
      uint32_t bits = jax_bits(keyA[it], keyB[it], (uint32_t)(row * MCAND + tid));
      float u = fmaxf(LO, fmaf(u01_from_bits(bits), 2.0f, LO));
      angs[tid] = fmaf(musd[1], SQRT2 * erfinv_f32(u), musd[0]);
    }
    __syncthreads();
  }
}

extern "C" void kernel_launch(void* const* d_in, const int* in_sizes, int n_in,
                              void* d_out, int out_size) {
  const float* states = (const float*)d_in[0];
  const float* W1     = (const float*)d_in[1];
  const float* b1     = (const float*)d_in[2];
  const float* W2     = (const float*)d_in[3];
  const float* b2     = (const float*)d_in[4];
  const float* W3     = (const float*)d_in[5];
  const float* b3     = (const float*)d_in[6];
  float* out          = (float*)d_out;
  (void)in_sizes; (void)n_in; (void)out_size;

  const size_t SMEM_BYTES =
      sizeof(float2) * NREG * HID +        // AB table
      sizeof(float) * (HID + 1) +          // tsort (+sentinel)
      sizeof(float) * HID * 4 +            // tun, a, b, w3
      sizeof(int) * HID +                  // ord
      sizeof(float) * MCAND * 2 +          // qs, angs
      sizeof(uint32_t) * (NITER - 1) * 2 + // keys
      sizeof(float) * 2 + 64;              // musd + pad

  cudaFuncSetAttribute(cem_kernel, cudaFuncAttributeMaxDynamicSharedMemorySize,
                       (int)SMEM_BYTES);
  cem_kernel<<<NBATCH, TPB, SMEM_BYTES>>>(states, W1, b1, W2, b2, W3, b3, out);
}